// round 15
// baseline (speedup 1.0000x reference)
#include <cuda_runtime.h>
#include <mma.h>
using namespace nvcuda;

#define N_NODES 20000
#define N_EDGES 320000
#define HID 256
#define NF (N_NODES * HID)
#define ZSTRIPES 32

// ---------------- scratch (device globals; no allocation allowed) ----------
__device__ float g_deg[2 * N_NODES];
__device__ float g_dinv[2 * N_NODES];
__device__ float g_w[2 * N_NODES];
__device__ float g_zp[ZSTRIPES * HID];   // striped z partials
__device__ float g_Wt[2 * HID * HID];    // tf32-rounded W1, W2
__device__ float g_bufB[2 * NF];         // xw (gemm output), both branches
__device__ float g_bufC[2 * NF];         // layer-1 output (post-relu)
__device__ int   g_rowptr[2 * (N_NODES + 1)];
__device__ int   g_cursor[2 * N_NODES];
__device__ int2  g_csr[2 * N_EDGES];     // packed (src, coef-bits)

__device__ __forceinline__ float to_tf32(float x) {
    unsigned u;
    asm("cvt.rna.tf32.f32 %0, %1;" : "=r"(u) : "f"(x));
    return __uint_as_float(u);
}

// ---------------- batched degree + W pre-rounding (fused) ------------------
#define DEG_BLOCKS ((2 * N_EDGES + 255) / 256)   // 2500
__global__ void k_degW(const int* __restrict__ dst0, const int* __restrict__ dst1,
                       const float* __restrict__ W1, const float* __restrict__ W2) {
    int b = blockIdx.x;
    if (b < DEG_BLOCKS) {
        int e = b * 256 + threadIdx.x;
        if (e >= 2 * N_EDGES) return;
        int br = e >= N_EDGES;
        int le = e - br * N_EDGES;
        int d = br ? dst1[le] : dst0[le];
        atomicAdd(&g_deg[br * N_NODES + d], 1.0f);
    } else {
        int i = (b - DEG_BLOCKS) * 256 + threadIdx.x;   // 65536 elements each
        g_Wt[i] = to_tf32(W1[i]);
        g_Wt[HID * HID + i] = to_tf32(W2[i]);
    }
}

// ---------------- per-branch scan + dinv + w-self (one block per branch) ---
__global__ __launch_bounds__(1024) void k_scan() {
    __shared__ int partial[1024];
    const int br = blockIdx.x;
    const int t = threadIdx.x;
    const int CH = 20;  // 1024*20 >= 20000
    int local[CH];
    int base = t * CH;
    int s = 0;
#pragma unroll
    for (int i = 0; i < CH; i++) {
        int idx = base + i;
        float d = (idx < N_NODES) ? g_deg[br * N_NODES + idx] : 0.f;
        local[i] = s;
        s += (int)d;
        if (idx < N_NODES) {
            float dv = rsqrtf(d + 1.0f);
            g_dinv[br * N_NODES + idx] = dv;
            g_w[br * N_NODES + idx] = dv * dv;
        }
    }
    partial[t] = s;
    __syncthreads();
    for (int off = 1; off < 1024; off <<= 1) {
        int v = (t >= off) ? partial[t - off] : 0;
        __syncthreads();
        partial[t] += v;
        __syncthreads();
    }
    int offset = (t > 0) ? partial[t - 1] : 0;
#pragma unroll
    for (int i = 0; i < CH; i++) {
        int idx = base + i;
        if (idx < N_NODES) {
            int v = offset + local[i];
            g_rowptr[br * (N_NODES + 1) + idx] = v;
            g_cursor[br * N_NODES + idx] = v;
        }
    }
    if (t == 1023) g_rowptr[br * (N_NODES + 1) + N_NODES] = partial[1023];
}

// ---------------- batched CSR fill (packed int2 + w[src] accumulation) -----
__global__ void k_fill(const int* __restrict__ src0, const int* __restrict__ dst0,
                       const int* __restrict__ src1, const int* __restrict__ dst1) {
    int e = blockIdx.x * blockDim.x + threadIdx.x;
    if (e >= 2 * N_EDGES) return;
    int br = e >= N_EDGES;
    int le = e - br * N_EDGES;
    int s = br ? src1[le] : src0[le];
    int d = br ? dst1[le] : dst0[le];
    float coef = g_dinv[br * N_NODES + s] * g_dinv[br * N_NODES + d];
    int pos = atomicAdd(&g_cursor[br * N_NODES + d], 1);
    g_csr[pos + br * N_EDGES] = make_int2(s, __float_as_int(coef));
    atomicAdd(&g_w[br * N_NODES + s], coef);
}

// ---------------- tf32 GEMM, 128x256 tile, 512 threads, KC=32 --------------
// Out[M,256] = A[M,256] @ Wt[256,256]; full output width per CTA.
// 16 warps as 4(row)x4(col): each warp 32 rows x 64 cols (2x4 frags).
// Register-prefetch double-buffered smem, one __syncthreads per k-chunk.
#define ASZ (128 * 36)             // one A stage (floats)
#define BSZ (32 * 260)             // one B stage (floats), 256+4 pad
#define GEMM_SMEM ((2 * ASZ + 2 * BSZ) * 4)   // 103424 bytes

__global__ __launch_bounds__(512) void k_gemm_tc(const float* __restrict__ A0,
                                                 const float* __restrict__ A1,
                                                 const float* __restrict__ Wt,
                                                 float* __restrict__ Out, int M) {
    extern __shared__ float sm[];
    float* As = sm;                 // [2][128][36]
    float* Bs = sm + 2 * ASZ;       // [2][32][260]

    const int tid = threadIdx.x;
    const int wid = tid >> 5;
    const float* A = blockIdx.z ? A1 : A0;
    float* C = Out + (long)blockIdx.z * M * 256;
    const int row0 = blockIdx.y * 128;

    wmma::fragment<wmma::accumulator, 16, 16, 8, float> c[2][4];
#pragma unroll
    for (int i = 0; i < 2; i++)
#pragma unroll
        for (int j = 0; j < 4; j++) wmma::fill_fragment(c[i][j], 0.f);

    // load mapping: A 128x32 per chunk, 8 floats/thread; B 32x256, 16/thread
    const int ar = tid >> 2;            // 0..127
    const int ac = (tid & 3) * 8;       // 0,8,16,24
    const int brw = tid >> 4;           // 0..31
    const int bc = (tid & 15) * 16;     // 0..240
    const int gr = row0 + ar;
    const bool av = gr < M;
    const float* aptr = A + (long)(av ? gr : 0) * 256 + ac;
    const float* bptr = Wt + (long)brw * 256 + bc;

    float4 pa[2], pb[4];
    const float4 z4 = make_float4(0.f, 0.f, 0.f, 0.f);

#define LD_CHUNK(kt) do { \
    if (av) { \
        pa[0] = *(const float4*)(aptr + (kt)); \
        pa[1] = *(const float4*)(aptr + (kt) + 4); \
    } else { pa[0] = z4; pa[1] = z4; } \
    pb[0] = *(const float4*)(bptr + (long)(kt) * 256); \
    pb[1] = *(const float4*)(bptr + (long)(kt) * 256 + 4); \
    pb[2] = *(const float4*)(bptr + (long)(kt) * 256 + 8); \
    pb[3] = *(const float4*)(bptr + (long)(kt) * 256 + 12); \
} while (0)

#define ST_CHUNK(st) do { \
    float* ad = As + (st) * ASZ + ar * 36 + ac; \
    _Pragma("unroll") \
    for (int q = 0; q < 2; q++) { \
        float4 v = pa[q]; \
        ad[q * 4 + 0] = to_tf32(v.x); ad[q * 4 + 1] = to_tf32(v.y); \
        ad[q * 4 + 2] = to_tf32(v.z); ad[q * 4 + 3] = to_tf32(v.w); \
    } \
    float* bd = Bs + (st) * BSZ + brw * 260 + bc; \
    _Pragma("unroll") \
    for (int q = 0; q < 4; q++) *(float4*)(bd + q * 4) = pb[q]; \
} while (0)

    LD_CHUNK(0);
    ST_CHUNK(0);
    __syncthreads();

    const int wrow = (wid >> 2) * 32;   // warp's row offset in tile
    const int wcol = (wid & 3) * 64;    // warp's col offset in tile

    for (int ci = 0; ci < 8; ci++) {
        const int cur = ci & 1;
        if (ci < 7) LD_CHUNK((ci + 1) * 32);   // prefetch overlaps mma

        const float* as = As + cur * ASZ + wrow * 36;
        const float* bs = Bs + cur * BSZ + wcol;
#pragma unroll
        for (int kk = 0; kk < 32; kk += 8) {
            wmma::fragment<wmma::matrix_a, 16, 16, 8, wmma::precision::tf32, wmma::row_major> a0, a1;
            wmma::load_matrix_sync(a0, as + kk, 36);
            wmma::load_matrix_sync(a1, as + 16 * 36 + kk, 36);
#pragma unroll
            for (int j = 0; j < 4; j++) {
                wmma::fragment<wmma::matrix_b, 16, 16, 8, wmma::precision::tf32, wmma::row_major> b;
                wmma::load_matrix_sync(b, bs + kk * 260 + j * 16, 260);
                wmma::mma_sync(c[0][j], a0, b, c[0][j]);
                wmma::mma_sync(c[1][j], a1, b, c[1][j]);
            }
        }
        if (ci < 7) ST_CHUNK(cur ^ 1);
        __syncthreads();
    }

#pragma unroll
    for (int i = 0; i < 2; i++) {
        const int wr = row0 + wrow + i * 16;
        if (wr < M) {  // M multiple of 16: frag rows all-in or all-out
#pragma unroll
            for (int j = 0; j < 4; j++)
                wmma::store_matrix_sync(C + (long)wr * 256 + wcol + j * 16,
                                        c[i][j], 256, wmma::mem_row_major);
        }
    }
}

// ---------------- batched CSR gather, float4 lanes, packed csr -------------
// 4 nodes per block, 64 threads each.
// ZRED=false: C[row] = relu(sum coef*xw[src] + self + b)
// ZRED=true:  g_zp[stripe][c] += w[row] * relu(...)  (layer-3 collapse fused)
template <bool ZRED>
__global__ __launch_bounds__(256) void k_gather(const float* __restrict__ xw,
                                                const float* __restrict__ bias,
                                                float* __restrict__ C) {
    __shared__ float sz[HID];
    if (ZRED) {
        sz[threadIdx.x] = 0.f;
        __syncthreads();
    }
    const int g = threadIdx.x >> 6;
    const int t = threadIdx.x & 63;
    const int row = blockIdx.x * 4 + g;          // grid*4 == 2*N_NODES exactly
    const int br = row >= N_NODES;
    const int n = row - br * N_NODES;
    const int* rowptr = g_rowptr + br * (N_NODES + 1);
    const int beg = rowptr[n];
    const int end = rowptr[n + 1];
    const float di = g_dinv[row];
    const float* xwb = xw + (long)br * NF;
    const int2* csr = g_csr + br * N_EDGES;

    const float dd = di * di;
    float4 bs = *(const float4*)(bias + t * 4);
    float4 sf = *(const float4*)(xwb + (long)n * 256 + t * 4);
    float4 acc0, acc1, acc2, acc3;
    acc0.x = fmaf(sf.x, dd, bs.x); acc0.y = fmaf(sf.y, dd, bs.y);
    acc0.z = fmaf(sf.z, dd, bs.z); acc0.w = fmaf(sf.w, dd, bs.w);
    acc1 = make_float4(0.f, 0.f, 0.f, 0.f);
    acc2 = acc1; acc3 = acc1;

    int i = beg;
    for (; i + 4 <= end; i += 4) {
        int2 e0 = csr[i], e1 = csr[i + 1], e2 = csr[i + 2], e3 = csr[i + 3];
        float c0 = __int_as_float(e0.y), c1 = __int_as_float(e1.y);
        float c2 = __int_as_float(e2.y), c3 = __int_as_float(e3.y);
        float4 v0 = *(const float4*)(xwb + (long)e0.x * 256 + t * 4);
        float4 v1 = *(const float4*)(xwb + (long)e1.x * 256 + t * 4);
        float4 v2 = *(const float4*)(xwb + (long)e2.x * 256 + t * 4);
        float4 v3 = *(const float4*)(xwb + (long)e3.x * 256 + t * 4);
        acc0.x = fmaf(c0, v0.x, acc0.x); acc0.y = fmaf(c0, v0.y, acc0.y);
        acc0.z = fmaf(c0, v0.z, acc0.z); acc0.w = fmaf(c0, v0.w, acc0.w);
        acc1.x = fmaf(c1, v1.x, acc1.x); acc1.y = fmaf(c1, v1.y, acc1.y);
        acc1.z = fmaf(c1, v1.z, acc1.z); acc1.w = fmaf(c1, v1.w, acc1.w);
        acc2.x = fmaf(c2, v2.x, acc2.x); acc2.y = fmaf(c2, v2.y, acc2.y);
        acc2.z = fmaf(c2, v2.z, acc2.z); acc2.w = fmaf(c2, v2.w, acc2.w);
        acc3.x = fmaf(c3, v3.x, acc3.x); acc3.y = fmaf(c3, v3.y, acc3.y);
        acc3.z = fmaf(c3, v3.z, acc3.z); acc3.w = fmaf(c3, v3.w, acc3.w);
    }
    for (; i < end; i++) {
        int2 e = csr[i];
        float cc = __int_as_float(e.y);
        float4 v = *(const float4*)(xwb + (long)e.x * 256 + t * 4);
        acc0.x = fmaf(cc, v.x, acc0.x); acc0.y = fmaf(cc, v.y, acc0.y);
        acc0.z = fmaf(cc, v.z, acc0.z); acc0.w = fmaf(cc, v.w, acc0.w);
    }
    float4 o;
    o.x = fmaxf(acc0.x + acc1.x + acc2.x + acc3.x, 0.f);
    o.y = fmaxf(acc0.y + acc1.y + acc2.y + acc3.y, 0.f);
    o.z = fmaxf(acc0.z + acc1.z + acc2.z + acc3.z, 0.f);
    o.w = fmaxf(acc0.w + acc1.w + acc2.w + acc3.w, 0.f);

    if (ZRED) {
        const float wr = __ldg(&g_w[row]);
        atomicAdd(&sz[t * 4 + 0], wr * o.x);
        atomicAdd(&sz[t * 4 + 1], wr * o.y);
        atomicAdd(&sz[t * 4 + 2], wr * o.z);
        atomicAdd(&sz[t * 4 + 3], wr * o.w);
        __syncthreads();
        // striped global reduction: 32x fewer collisions per address
        atomicAdd(&g_zp[(blockIdx.x & (ZSTRIPES - 1)) * HID + threadIdx.x],
                  sz[threadIdx.x]);
    } else {
        *(float4*)(C + (long)row * 256 + t * 4) = o;
    }
}

// pooled = (z @ W3)/(2N) + b3 ; out = pooled @ Wl + bl
__global__ void k_final(const float* __restrict__ W3, const float* __restrict__ b3,
                        const float* __restrict__ Wl, const float* __restrict__ bl,
                        float* __restrict__ out) {
    int j = threadIdx.x;
    __shared__ float sz[HID];
    __shared__ float so[8];
    float zs = 0.f;
#pragma unroll
    for (int s = 0; s < ZSTRIPES; s++)
        zs += g_zp[s * HID + j];
    sz[j] = zs;
    if (j < 8) so[j] = 0.f;
    __syncthreads();

    float acc = 0.f;
#pragma unroll 8
    for (int k = 0; k < HID; k++)
        acc = fmaf(sz[k], W3[k * HID + j], acc);
    float pv = acc * (1.0f / (2.0f * N_NODES)) + b3[j];

#pragma unroll
    for (int c = 0; c < 5; c++)
        atomicAdd(&so[c], pv * Wl[j * 5 + c]);
    __syncthreads();
    if (j < 5) out[j] = so[j] + bl[j];
}

// ---------------------------------------------------------------------------
extern "C" void kernel_launch(void* const* d_in, const int* in_sizes, int n_in,
                              void* d_out, int out_size) {
    const float* x1 = (const float*)d_in[0];
    const int*   ei1 = (const int*)d_in[1];
    const float* x2 = (const float*)d_in[2];
    const int*   ei2 = (const int*)d_in[3];
    const float* W1 = (const float*)d_in[4];
    const float* b1 = (const float*)d_in[5];
    const float* W2 = (const float*)d_in[6];
    const float* b2 = (const float*)d_in[7];
    const float* W3 = (const float*)d_in[8];
    const float* b3 = (const float*)d_in[9];
    const float* Wl = (const float*)d_in[10];
    const float* bl = (const float*)d_in[11];
    float* out = (float*)d_out;

    float *deg, *zp, *Wt, *B, *C;
    cudaGetSymbolAddress((void**)&deg, g_deg);
    cudaGetSymbolAddress((void**)&zp,  g_zp);
    cudaGetSymbolAddress((void**)&Wt,  g_Wt);
    cudaGetSymbolAddress((void**)&B,   g_bufB);
    cudaGetSymbolAddress((void**)&C,   g_bufC);

    cudaFuncSetAttribute(k_gemm_tc, cudaFuncAttributeMaxDynamicSharedMemorySize, GEMM_SMEM);

    const int* src0 = ei1;
    const int* dst0 = ei1 + N_EDGES;
    const int* src1 = ei2;
    const int* dst1 = ei2 + N_EDGES;

    const int e2_blocks = (2 * N_EDGES + 255) / 256;
    const dim3 gemm1_grid(1, (N_NODES + 127) / 128, 2);       // 157 x 2 branches
    const dim3 gemm2_grid(1, (2 * N_NODES + 127) / 128, 1);   // 313

    cudaMemsetAsync(zp, 0, ZSTRIPES * HID * sizeof(float));
    cudaMemsetAsync(deg, 0, 2 * N_NODES * sizeof(float));

    // graph preprocessing (deg + W-rounding fused; both branches batched)
    k_degW<<<DEG_BLOCKS + HID * HID / 256, 256>>>(dst0, dst1, W1, W2);
    k_scan<<<2, 1024>>>();
    k_fill<<<e2_blocks, 256>>>(src0, dst0, src1, dst1);

    // layer 1: both branch GEMMs in one launch, batched gather (writes relu)
    k_gemm_tc<<<gemm1_grid, 512, GEMM_SMEM>>>(x1, x2, Wt, B, N_NODES);
    k_gather<false><<<(2 * N_NODES) / 4, 256>>>(B, b1, C);

    // layer 2: one batched GEMM over both branches; gather fuses the
    // collapsed layer-3 reduction into striped z partials — no C write.
    k_gemm_tc<<<gemm2_grid, 512, GEMM_SMEM>>>(C, C, Wt + HID * HID, B, 2 * N_NODES);
    k_gather<true><<<(2 * N_NODES) / 4, 256>>>(B, b2, C);

    k_final<<<1, 256>>>(W3, b3, Wl, bl, out);
}

// round 16
// speedup vs baseline: 1.3961x; 1.3961x over previous
#include <cuda_runtime.h>
#include <cuda_bf16.h>
#include <mma.h>
using namespace nvcuda;

#define N_NODES 20000
#define N_EDGES 320000
#define HID 256
#define NF (N_NODES * HID)
#define ZSTRIPES 32

// ---------------- scratch (device globals; no allocation allowed) ----------
__device__ float g_deg[2 * N_NODES];
__device__ float g_dinv[2 * N_NODES];
__device__ float g_w[2 * N_NODES];
__device__ float g_zp[ZSTRIPES * HID];        // striped z partials
__device__ __nv_bfloat16 g_Wbf[2 * HID * HID];  // bf16 W1, W2
__device__ float g_bufB[2 * NF];              // xw (gemm output), both branches
__device__ float g_bufC[2 * NF];              // layer-1 output (post-relu)
__device__ int   g_rowptr[2 * (N_NODES + 1)];
__device__ int   g_cursor[2 * N_NODES];
__device__ int2  g_csr[2 * N_EDGES];          // packed (src, coef-bits)

// ---------------- batched degree + W bf16 conversion (fused) ---------------
#define DEG_BLOCKS ((2 * N_EDGES + 255) / 256)   // 2500
__global__ void k_degW(const int* __restrict__ dst0, const int* __restrict__ dst1,
                       const float* __restrict__ W1, const float* __restrict__ W2) {
    int b = blockIdx.x;
    if (b < DEG_BLOCKS) {
        int e = b * 256 + threadIdx.x;
        if (e >= 2 * N_EDGES) return;
        int br = e >= N_EDGES;
        int le = e - br * N_EDGES;
        int d = br ? dst1[le] : dst0[le];
        atomicAdd(&g_deg[br * N_NODES + d], 1.0f);
    } else {
        int i = (b - DEG_BLOCKS) * 256 + threadIdx.x;   // 65536 elements each
        g_Wbf[i] = __float2bfloat16(W1[i]);
        g_Wbf[HID * HID + i] = __float2bfloat16(W2[i]);
    }
}

// ---------------- per-branch scan + dinv + w-self (one block per branch) ---
__global__ __launch_bounds__(1024) void k_scan() {
    __shared__ int partial[1024];
    const int br = blockIdx.x;
    const int t = threadIdx.x;
    const int CH = 20;  // 1024*20 >= 20000
    int local[CH];
    int base = t * CH;
    int s = 0;
#pragma unroll
    for (int i = 0; i < CH; i++) {
        int idx = base + i;
        float d = (idx < N_NODES) ? g_deg[br * N_NODES + idx] : 0.f;
        local[i] = s;
        s += (int)d;
        if (idx < N_NODES) {
            float dv = rsqrtf(d + 1.0f);
            g_dinv[br * N_NODES + idx] = dv;
            g_w[br * N_NODES + idx] = dv * dv;
        }
    }
    partial[t] = s;
    __syncthreads();
    for (int off = 1; off < 1024; off <<= 1) {
        int v = (t >= off) ? partial[t - off] : 0;
        __syncthreads();
        partial[t] += v;
        __syncthreads();
    }
    int offset = (t > 0) ? partial[t - 1] : 0;
#pragma unroll
    for (int i = 0; i < CH; i++) {
        int idx = base + i;
        if (idx < N_NODES) {
            int v = offset + local[i];
            g_rowptr[br * (N_NODES + 1) + idx] = v;
            g_cursor[br * N_NODES + idx] = v;
        }
    }
    if (t == 1023) g_rowptr[br * (N_NODES + 1) + N_NODES] = partial[1023];
}

// ---------------- batched CSR fill (packed int2 + w[src] accumulation) -----
__global__ void k_fill(const int* __restrict__ src0, const int* __restrict__ dst0,
                       const int* __restrict__ src1, const int* __restrict__ dst1) {
    int e = blockIdx.x * blockDim.x + threadIdx.x;
    if (e >= 2 * N_EDGES) return;
    int br = e >= N_EDGES;
    int le = e - br * N_EDGES;
    int s = br ? src1[le] : src0[le];
    int d = br ? dst1[le] : dst0[le];
    float coef = g_dinv[br * N_NODES + s] * g_dinv[br * N_NODES + d];
    int pos = atomicAdd(&g_cursor[br * N_NODES + d], 1);
    g_csr[pos + br * N_EDGES] = make_int2(s, __float_as_int(coef));
    atomicAdd(&g_w[br * N_NODES + s], coef);
}

// ---------------- bf16 GEMM, 128x256 tile, 512 threads, KC=32 --------------
// Out[M,256] = A[M,256] @ Wbf[256,256] (bf16 inputs, fp32 accumulate).
// 16 warps as 4(row)x4(col): each warp 32 rows x 64 cols (2x4 frags).
// m16n16k16: half the HMMA count and half the fragment LDS of the tf32 path.
#define A_LD 40                    // A stage row stride (bf16 elems, 80B)
#define B_LD 264                   // B stage row stride (bf16 elems, 528B)
#define ASZ (128 * A_LD)           // one A stage (bf16 elems)
#define BSZ (32 * B_LD)            // one B stage (bf16 elems)
#define GEMM_SMEM ((2 * ASZ + 2 * BSZ) * 2)   // 54272 bytes

__global__ __launch_bounds__(512) void k_gemm_tc(const float* __restrict__ A0,
                                                 const float* __restrict__ A1,
                                                 const __nv_bfloat16* __restrict__ Wb,
                                                 float* __restrict__ Out, int M) {
    extern __shared__ __nv_bfloat16 smb[];
    __nv_bfloat16* As = smb;                 // [2][128][A_LD]
    __nv_bfloat16* Bs = smb + 2 * ASZ;       // [2][32][B_LD]

    const int tid = threadIdx.x;
    const int wid = tid >> 5;
    const float* A = blockIdx.z ? A1 : A0;
    float* C = Out + (long)blockIdx.z * M * 256;
    const int row0 = blockIdx.y * 128;

    wmma::fragment<wmma::accumulator, 16, 16, 16, float> c[2][4];
#pragma unroll
    for (int i = 0; i < 2; i++)
#pragma unroll
        for (int j = 0; j < 4; j++) wmma::fill_fragment(c[i][j], 0.f);

    // load mapping: A 128x32 per chunk, 8 floats/thread; B 32x256, 16/thread
    const int ar = tid >> 2;            // 0..127
    const int ac = (tid & 3) * 8;       // 0,8,16,24
    const int brw = tid >> 4;           // 0..31
    const int bc = (tid & 15) * 16;     // 0..240
    const int gr = row0 + ar;
    const bool av = gr < M;
    const float* aptr = A + (long)(av ? gr : 0) * 256 + ac;
    const __nv_bfloat16* bptr = Wb + (long)brw * 256 + bc;

    float4 pa[2];
    uint4 pbv[2];
    const float4 z4 = make_float4(0.f, 0.f, 0.f, 0.f);

#define LD_CHUNK(kt) do { \
    if (av) { \
        pa[0] = *(const float4*)(aptr + (kt)); \
        pa[1] = *(const float4*)(aptr + (kt) + 4); \
    } else { pa[0] = z4; pa[1] = z4; } \
    pbv[0] = *(const uint4*)(bptr + (long)(kt) * 256); \
    pbv[1] = *(const uint4*)(bptr + (long)(kt) * 256 + 8); \
} while (0)

#define ST_CHUNK(st) do { \
    __nv_bfloat16* ad = As + (st) * ASZ + ar * A_LD + ac; \
    uint4 apk; \
    { \
        __nv_bfloat162 h0 = __float22bfloat162_rn(make_float2(pa[0].x, pa[0].y)); \
        __nv_bfloat162 h1 = __float22bfloat162_rn(make_float2(pa[0].z, pa[0].w)); \
        __nv_bfloat162 h2 = __float22bfloat162_rn(make_float2(pa[1].x, pa[1].y)); \
        __nv_bfloat162 h3 = __float22bfloat162_rn(make_float2(pa[1].z, pa[1].w)); \
        apk.x = *(unsigned*)&h0; apk.y = *(unsigned*)&h1; \
        apk.z = *(unsigned*)&h2; apk.w = *(unsigned*)&h3; \
    } \
    *(uint4*)ad = apk; \
    __nv_bfloat16* bd = Bs + (st) * BSZ + brw * B_LD + bc; \
    *(uint4*)bd = pbv[0]; \
    *(uint4*)(bd + 8) = pbv[1]; \
} while (0)

    LD_CHUNK(0);
    ST_CHUNK(0);
    __syncthreads();

    const int wrow = (wid >> 2) * 32;   // warp's row offset in tile
    const int wcol = (wid & 3) * 64;    // warp's col offset in tile

    for (int ci = 0; ci < 8; ci++) {
        const int cur = ci & 1;
        if (ci < 7) LD_CHUNK((ci + 1) * 32);   // prefetch overlaps mma

        const __nv_bfloat16* as = As + cur * ASZ + wrow * A_LD;
        const __nv_bfloat16* bs = Bs + cur * BSZ + wcol;
#pragma unroll
        for (int kk = 0; kk < 32; kk += 16) {
            wmma::fragment<wmma::matrix_a, 16, 16, 16, __nv_bfloat16, wmma::row_major> a0, a1;
            wmma::load_matrix_sync(a0, as + kk, A_LD);
            wmma::load_matrix_sync(a1, as + 16 * A_LD + kk, A_LD);
#pragma unroll
            for (int j = 0; j < 4; j++) {
                wmma::fragment<wmma::matrix_b, 16, 16, 16, __nv_bfloat16, wmma::row_major> b;
                wmma::load_matrix_sync(b, bs + kk * B_LD + j * 16, B_LD);
                wmma::mma_sync(c[0][j], a0, b, c[0][j]);
                wmma::mma_sync(c[1][j], a1, b, c[1][j]);
            }
        }
        if (ci < 7) ST_CHUNK(cur ^ 1);
        __syncthreads();
    }

#pragma unroll
    for (int i = 0; i < 2; i++) {
        const int wr = row0 + wrow + i * 16;
        if (wr < M) {  // M multiple of 16: frag rows all-in or all-out
#pragma unroll
            for (int j = 0; j < 4; j++)
                wmma::store_matrix_sync(C + (long)wr * 256 + wcol + j * 16,
                                        c[i][j], 256, wmma::mem_row_major);
        }
    }
}

// ---------------- batched CSR gather, float4 lanes, packed csr -------------
// 4 nodes per block, 64 threads each.
// ZRED=false: C[row] = relu(sum coef*xw[src] + self + b)
// ZRED=true:  g_zp[stripe][c] += w[row] * relu(...)  (layer-3 collapse fused)
template <bool ZRED>
__global__ __launch_bounds__(256) void k_gather(const float* __restrict__ xw,
                                                const float* __restrict__ bias,
                                                float* __restrict__ C) {
    __shared__ float sz[HID];
    if (ZRED) {
        sz[threadIdx.x] = 0.f;
        __syncthreads();
    }
    const int g = threadIdx.x >> 6;
    const int t = threadIdx.x & 63;
    const int row = blockIdx.x * 4 + g;          // grid*4 == 2*N_NODES exactly
    const int br = row >= N_NODES;
    const int n = row - br * N_NODES;
    const int* rowptr = g_rowptr + br * (N_NODES + 1);
    const int beg = rowptr[n];
    const int end = rowptr[n + 1];
    const float di = g_dinv[row];
    const float* xwb = xw + (long)br * NF;
    const int2* csr = g_csr + br * N_EDGES;

    const float dd = di * di;
    float4 bs = *(const float4*)(bias + t * 4);
    float4 sf = *(const float4*)(xwb + (long)n * 256 + t * 4);
    float4 acc0, acc1, acc2, acc3;
    acc0.x = fmaf(sf.x, dd, bs.x); acc0.y = fmaf(sf.y, dd, bs.y);
    acc0.z = fmaf(sf.z, dd, bs.z); acc0.w = fmaf(sf.w, dd, bs.w);
    acc1 = make_float4(0.f, 0.f, 0.f, 0.f);
    acc2 = acc1; acc3 = acc1;

    int i = beg;
    for (; i + 4 <= end; i += 4) {
        int2 e0 = csr[i], e1 = csr[i + 1], e2 = csr[i + 2], e3 = csr[i + 3];
        float c0 = __int_as_float(e0.y), c1 = __int_as_float(e1.y);
        float c2 = __int_as_float(e2.y), c3 = __int_as_float(e3.y);
        float4 v0 = *(const float4*)(xwb + (long)e0.x * 256 + t * 4);
        float4 v1 = *(const float4*)(xwb + (long)e1.x * 256 + t * 4);
        float4 v2 = *(const float4*)(xwb + (long)e2.x * 256 + t * 4);
        float4 v3 = *(const float4*)(xwb + (long)e3.x * 256 + t * 4);
        acc0.x = fmaf(c0, v0.x, acc0.x); acc0.y = fmaf(c0, v0.y, acc0.y);
        acc0.z = fmaf(c0, v0.z, acc0.z); acc0.w = fmaf(c0, v0.w, acc0.w);
        acc1.x = fmaf(c1, v1.x, acc1.x); acc1.y = fmaf(c1, v1.y, acc1.y);
        acc1.z = fmaf(c1, v1.z, acc1.z); acc1.w = fmaf(c1, v1.w, acc1.w);
        acc2.x = fmaf(c2, v2.x, acc2.x); acc2.y = fmaf(c2, v2.y, acc2.y);
        acc2.z = fmaf(c2, v2.z, acc2.z); acc2.w = fmaf(c2, v2.w, acc2.w);
        acc3.x = fmaf(c3, v3.x, acc3.x); acc3.y = fmaf(c3, v3.y, acc3.y);
        acc3.z = fmaf(c3, v3.z, acc3.z); acc3.w = fmaf(c3, v3.w, acc3.w);
    }
    for (; i < end; i++) {
        int2 e = csr[i];
        float cc = __int_as_float(e.y);
        float4 v = *(const float4*)(xwb + (long)e.x * 256 + t * 4);
        acc0.x = fmaf(cc, v.x, acc0.x); acc0.y = fmaf(cc, v.y, acc0.y);
        acc0.z = fmaf(cc, v.z, acc0.z); acc0.w = fmaf(cc, v.w, acc0.w);
    }
    float4 o;
    o.x = fmaxf(acc0.x + acc1.x + acc2.x + acc3.x, 0.f);
    o.y = fmaxf(acc0.y + acc1.y + acc2.y + acc3.y, 0.f);
    o.z = fmaxf(acc0.z + acc1.z + acc2.z + acc3.z, 0.f);
    o.w = fmaxf(acc0.w + acc1.w + acc2.w + acc3.w, 0.f);

    if (ZRED) {
        const float wr = __ldg(&g_w[row]);
        atomicAdd(&sz[t * 4 + 0], wr * o.x);
        atomicAdd(&sz[t * 4 + 1], wr * o.y);
        atomicAdd(&sz[t * 4 + 2], wr * o.z);
        atomicAdd(&sz[t * 4 + 3], wr * o.w);
        __syncthreads();
        // striped global reduction: 32x fewer collisions per address
        atomicAdd(&g_zp[(blockIdx.x & (ZSTRIPES - 1)) * HID + threadIdx.x],
                  sz[threadIdx.x]);
    } else {
        *(float4*)(C + (long)row * 256 + t * 4) = o;
    }
}

// pooled = (z @ W3)/(2N) + b3 ; out = pooled @ Wl + bl
__global__ void k_final(const float* __restrict__ W3, const float* __restrict__ b3,
                        const float* __restrict__ Wl, const float* __restrict__ bl,
                        float* __restrict__ out) {
    int j = threadIdx.x;
    __shared__ float sz[HID];
    __shared__ float so[8];
    float zs = 0.f;
#pragma unroll
    for (int s = 0; s < ZSTRIPES; s++)
        zs += g_zp[s * HID + j];
    sz[j] = zs;
    if (j < 8) so[j] = 0.f;
    __syncthreads();

    float acc = 0.f;
#pragma unroll 8
    for (int k = 0; k < HID; k++)
        acc = fmaf(sz[k], W3[k * HID + j], acc);
    float pv = acc * (1.0f / (2.0f * N_NODES)) + b3[j];

#pragma unroll
    for (int c = 0; c < 5; c++)
        atomicAdd(&so[c], pv * Wl[j * 5 + c]);
    __syncthreads();
    if (j < 5) out[j] = so[j] + bl[j];
}

// ---------------------------------------------------------------------------
extern "C" void kernel_launch(void* const* d_in, const int* in_sizes, int n_in,
                              void* d_out, int out_size) {
    const float* x1 = (const float*)d_in[0];
    const int*   ei1 = (const int*)d_in[1];
    const float* x2 = (const float*)d_in[2];
    const int*   ei2 = (const int*)d_in[3];
    const float* W1 = (const float*)d_in[4];
    const float* b1 = (const float*)d_in[5];
    const float* W2 = (const float*)d_in[6];
    const float* b2 = (const float*)d_in[7];
    const float* W3 = (const float*)d_in[8];
    const float* b3 = (const float*)d_in[9];
    const float* Wl = (const float*)d_in[10];
    const float* bl = (const float*)d_in[11];
    float* out = (float*)d_out;

    float *deg, *zp, *B, *C;
    __nv_bfloat16* Wb;
    cudaGetSymbolAddress((void**)&deg, g_deg);
    cudaGetSymbolAddress((void**)&zp,  g_zp);
    cudaGetSymbolAddress((void**)&Wb,  g_Wbf);
    cudaGetSymbolAddress((void**)&B,   g_bufB);
    cudaGetSymbolAddress((void**)&C,   g_bufC);

    cudaFuncSetAttribute(k_gemm_tc, cudaFuncAttributeMaxDynamicSharedMemorySize, GEMM_SMEM);

    const int* src0 = ei1;
    const int* dst0 = ei1 + N_EDGES;
    const int* src1 = ei2;
    const int* dst1 = ei2 + N_EDGES;

    const int e2_blocks = (2 * N_EDGES + 255) / 256;
    const dim3 gemm1_grid(1, (N_NODES + 127) / 128, 2);       // 157 x 2 branches
    const dim3 gemm2_grid(1, (2 * N_NODES + 127) / 128, 1);   // 313

    cudaMemsetAsync(zp, 0, ZSTRIPES * HID * sizeof(float));
    cudaMemsetAsync(deg, 0, 2 * N_NODES * sizeof(float));

    // graph preprocessing (deg + W-bf16 fused; both branches batched)
    k_degW<<<DEG_BLOCKS + HID * HID / 256, 256>>>(dst0, dst1, W1, W2);
    k_scan<<<2, 1024>>>();
    k_fill<<<e2_blocks, 256>>>(src0, dst0, src1, dst1);

    // layer 1: both branch GEMMs in one launch, batched gather (writes relu)
    k_gemm_tc<<<gemm1_grid, 512, GEMM_SMEM>>>(x1, x2, Wb, B, N_NODES);
    k_gather<false><<<(2 * N_NODES) / 4, 256>>>(B, b1, C);

    // layer 2: one batched GEMM over both branches; gather fuses the
    // collapsed layer-3 reduction into striped z partials — no C write.
    k_gemm_tc<<<gemm2_grid, 512, GEMM_SMEM>>>(C, C, Wb + HID * HID, B, 2 * N_NODES);
    k_gather<true><<<(2 * N_NODES) / 4, 256>>>(B, b2, C);

    k_final<<<1, 256>>>(W3, b3, Wl, bl, out);
}